// round 1
// baseline (speedup 1.0000x reference)
#include <cuda_runtime.h>
#include <math.h>

// Problem constants (from reference): N=50000, E=800000, D_IN=128, EP=200000
#define NMAX 50000
#define DMAX 128

// Scratch (device globals: no allocation allowed in kernel_launch)
__device__ float g_hs[NMAX * DMAX];   // hs = (x@W) * dis[row]
__device__ float g_x[NMAX * DMAX];    // layer activations (ping)
__device__ float g_agg[NMAX * DMAX];  // edge aggregation
__device__ float g_dis[NMAX];         // deg -> rsqrt(deg+1)
__device__ float g_s[NMAX];           // final node scores

// ---------------------------------------------------------------------------
__global__ void zero_kernel(float* p, int n) {
    int i = blockIdx.x * blockDim.x + threadIdx.x;
    if (i < n) p[i] = 0.0f;
}

__global__ void deg_kernel(const int* __restrict__ dst, int E, float* deg) {
    int i = blockIdx.x * blockDim.x + threadIdx.x;
    if (i < E) atomicAdd(&deg[dst[i]], 1.0f);
}

__global__ void dis_kernel(float* d, int n) {
    int i = blockIdx.x * blockDim.x + threadIdx.x;
    if (i < n) d[i] = rsqrtf(d[i] + 1.0f);
}

// hs[row, col] = (A @ W)[row, col] * dis[row]
// A: n x din (row-major), W: din x dout (row-major)
#define TILE 16
__global__ void gemm_scale_kernel(const float* __restrict__ A,
                                  const float* __restrict__ W,
                                  const float* __restrict__ dis,
                                  float* __restrict__ out,
                                  int n, int din, int dout) {
    __shared__ float As[TILE][TILE];
    __shared__ float Ws[TILE][TILE + 1];
    int row = blockIdx.y * TILE + threadIdx.y;
    int col = blockIdx.x * TILE + threadIdx.x;
    float acc = 0.0f;
    for (int k0 = 0; k0 < din; k0 += TILE) {
        As[threadIdx.y][threadIdx.x] =
            (row < n) ? A[row * din + k0 + threadIdx.x] : 0.0f;  // din % TILE == 0
        Ws[threadIdx.y][threadIdx.x] =
            (col < dout) ? W[(k0 + threadIdx.y) * dout + col] : 0.0f;
        __syncthreads();
#pragma unroll
        for (int k = 0; k < TILE; k++)
            acc += As[threadIdx.y][k] * Ws[k][threadIdx.x];
        __syncthreads();
    }
    if (row < n && col < dout) out[row * dout + col] = acc * dis[row];
}

// agg[dst, f] += hs[src, f]  for every edge, every feature
__global__ void scatter_kernel(const int* __restrict__ src,
                               const int* __restrict__ dst,
                               const float* __restrict__ hs,
                               float* __restrict__ agg,
                               int total, int dout) {
    int i = blockIdx.x * blockDim.x + threadIdx.x;
    if (i >= total) return;
    int e = i / dout;
    int f = i - e * dout;
    int s = src[e];
    int d = dst[e];
    atomicAdd(&agg[d * dout + f], __ldg(&hs[s * dout + f]));
}

// out = relu(dis[row] * (agg + hs) + b[f])
__global__ void combine_kernel(const float* __restrict__ hs,
                               const float* __restrict__ agg,
                               const float* __restrict__ b,
                               const float* __restrict__ dis,
                               float* __restrict__ out,
                               int n, int dout) {
    int i = blockIdx.x * blockDim.x + threadIdx.x;
    if (i >= n * dout) return;
    int row = i / dout;
    int f = i - row * dout;
    float v = dis[row] * (agg[i] + hs[i]) + b[f];
    out[i] = v > 0.0f ? v : 0.0f;
}

// Fused MLP: x(32) -> relu(16) -> relu(8) -> sigmoid(1)
__global__ void mlp_kernel(const float* __restrict__ x,
                           const float* __restrict__ lw0, const float* __restrict__ lb0,
                           const float* __restrict__ lw1, const float* __restrict__ lb1,
                           const float* __restrict__ lw2, const float* __restrict__ lb2,
                           float* __restrict__ s, int n) {
    __shared__ float w0[32 * 16], b0[16], w1[16 * 8], b1[8], w2[8], b2s[1];
    int t = threadIdx.x;
    for (int j = t; j < 32 * 16; j += blockDim.x) w0[j] = lw0[j];
    for (int j = t; j < 16; j += blockDim.x) b0[j] = lb0[j];
    for (int j = t; j < 16 * 8; j += blockDim.x) w1[j] = lw1[j];
    for (int j = t; j < 8; j += blockDim.x) b1[j] = lb1[j];
    for (int j = t; j < 8; j += blockDim.x) w2[j] = lw2[j];
    if (t == 0) b2s[0] = lb2[0];
    __syncthreads();

    int i = blockIdx.x * blockDim.x + t;
    if (i >= n) return;

    float xv[32];
#pragma unroll
    for (int k = 0; k < 32; k++) xv[k] = x[i * 32 + k];

    float y1[16];
#pragma unroll
    for (int j = 0; j < 16; j++) {
        float a = b0[j];
#pragma unroll
        for (int k = 0; k < 32; k++) a += xv[k] * w0[k * 16 + j];
        y1[j] = a > 0.0f ? a : 0.0f;
    }
    float y2[8];
#pragma unroll
    for (int j = 0; j < 8; j++) {
        float a = b1[j];
#pragma unroll
        for (int k = 0; k < 16; k++) a += y1[k] * w1[k * 8 + j];
        y2[j] = a > 0.0f ? a : 0.0f;
    }
    float z = b2s[0];
#pragma unroll
    for (int k = 0; k < 8; k++) z += y2[k] * w2[k];
    s[i] = 1.0f / (1.0f + expf(-z));
}

__global__ void edge_score_kernel(const int* __restrict__ pe,
                                  const float* __restrict__ s,
                                  float* __restrict__ out, int ep) {
    int i = blockIdx.x * blockDim.x + threadIdx.x;
    if (i < ep) out[i] = s[pe[2 * i]] * s[pe[2 * i + 1]];
}

// ---------------------------------------------------------------------------
extern "C" void kernel_launch(void* const* d_in, const int* in_sizes, int n_in,
                              void* d_out, int out_size) {
    const float* x   = (const float*)d_in[0];
    const int* ei    = (const int*)d_in[1];
    const int* pe    = (const int*)d_in[2];
    const float* cw0 = (const float*)d_in[3];
    const float* cb0 = (const float*)d_in[4];
    const float* cw1 = (const float*)d_in[5];
    const float* cb1 = (const float*)d_in[6];
    const float* cw2 = (const float*)d_in[7];
    const float* cb2 = (const float*)d_in[8];
    const float* lw0 = (const float*)d_in[9];
    const float* lb0 = (const float*)d_in[10];
    const float* lw1 = (const float*)d_in[11];
    const float* lb1 = (const float*)d_in[12];
    const float* lw2 = (const float*)d_in[13];
    const float* lb2 = (const float*)d_in[14];
    float* out = (float*)d_out;

    const int N  = in_sizes[0] / 128;
    const int E  = in_sizes[1] / 2;
    const int EP = out_size;

    const int* src = ei;
    const int* dst = ei + E;

    float *hs, *xb, *agg, *dis, *sc;
    cudaGetSymbolAddress((void**)&hs, g_hs);
    cudaGetSymbolAddress((void**)&xb, g_x);
    cudaGetSymbolAddress((void**)&agg, g_agg);
    cudaGetSymbolAddress((void**)&dis, g_dis);
    cudaGetSymbolAddress((void**)&sc, g_s);

    const int B = 256;

    // degree -> dis (shared by all 3 conv layers)
    zero_kernel<<<(N + B - 1) / B, B>>>(dis, N);
    deg_kernel<<<(E + B - 1) / B, B>>>(dst, E, dis);
    dis_kernel<<<(N + B - 1) / B, B>>>(dis, N);

    const int conv_din[3]  = {128, 128, 64};
    const int conv_dout[3] = {128, 64, 32};
    const float* cw[3] = {cw0, cw1, cw2};
    const float* cb[3] = {cb0, cb1, cb2};

    const float* cur = x;
    for (int l = 0; l < 3; l++) {
        int din = conv_din[l], dout = conv_dout[l];

        dim3 gb((dout + TILE - 1) / TILE, (N + TILE - 1) / TILE);
        dim3 tb(TILE, TILE);
        gemm_scale_kernel<<<gb, tb>>>(cur, cw[l], dis, hs, N, din, dout);

        zero_kernel<<<(N * dout + B - 1) / B, B>>>(agg, N * dout);

        int total = E * dout;
        scatter_kernel<<<(total + B - 1) / B, B>>>(src, dst, hs, agg, total, dout);

        combine_kernel<<<(N * dout + B - 1) / B, B>>>(hs, agg, cb[l], dis, xb, N, dout);
        cur = xb;
    }

    mlp_kernel<<<(N + B - 1) / B, B>>>(xb, lw0, lb0, lw1, lb1, lw2, lb2, sc, N);
    edge_score_kernel<<<(EP + B - 1) / B, B>>>(pe, sc, out, EP);
}

// round 5
// speedup vs baseline: 3.1405x; 3.1405x over previous
#include <cuda_runtime.h>
#include <math.h>

#define NMAX 50000
#define EMAX 800000
#define DMAX 128

// Scratch (device globals; no allocation in kernel_launch)
__device__ float g_hs[NMAX * DMAX];    // hs = (x@W) * dis[row]
__device__ float g_x[NMAX * DMAX];     // layer activations
__device__ float g_dis[NMAX];          // rsqrt(deg+1)
__device__ float g_s[NMAX];            // node scores
__device__ int   g_counts[NMAX];       // in-degree histogram
__device__ int   g_offsets[NMAX + 1];  // CSR row offsets
__device__ int   g_cursor[NMAX];       // fill cursors
__device__ int   g_csr[EMAX];          // CSR src indices grouped by dst

// ---------------------------------------------------------------------------
__global__ void zero_int_kernel(int* p, int n) {
    int i = blockIdx.x * blockDim.x + threadIdx.x;
    if (i < n) p[i] = 0;
}

__global__ void hist_kernel(const int* __restrict__ dst, int E, int* counts) {
    int i = blockIdx.x * blockDim.x + threadIdx.x;
    if (i < E) atomicAdd(&counts[dst[i]], 1);
}

// Single-block exclusive scan of counts -> offsets/cursor; also dis = rsqrt(c+1)
__global__ void scan_kernel(const int* __restrict__ counts, int* offsets,
                            int* cursor, float* dis, int n) {
    __shared__ int sh[1024];
    __shared__ int carry;
    int t = threadIdx.x;
    if (t == 0) carry = 0;
    __syncthreads();
    for (int base = 0; base < n; base += 1024) {
        int i = base + t;
        int v = (i < n) ? counts[i] : 0;
        sh[t] = v;
        __syncthreads();
#pragma unroll
        for (int off = 1; off < 1024; off <<= 1) {
            int u = (t >= off) ? sh[t - off] : 0;
            __syncthreads();
            sh[t] += u;
            __syncthreads();
        }
        if (i < n) {
            int o = carry + sh[t] - v;  // exclusive
            offsets[i] = o;
            cursor[i] = o;
            dis[i] = rsqrtf((float)v + 1.0f);
        }
        __syncthreads();
        if (t == 1023) carry += sh[1023];
        __syncthreads();
    }
    if (t == 0) offsets[n] = carry;
}

__global__ void fill_kernel(const int* __restrict__ src,
                            const int* __restrict__ dst, int E,
                            int* cursor, int* csr) {
    int i = blockIdx.x * blockDim.x + threadIdx.x;
    if (i < E) {
        int pos = atomicAdd(&cursor[dst[i]], 1);
        csr[pos] = src[i];
    }
}

// ---------------------------------------------------------------------------
// Register-blocked SGEMM + row scale: out[r, c] = (A@W)[r, c] * dis[r]
// BM=64 rows/block, BN=DOUT (full width), BK=8, 256 threads.
template <int DIN, int DOUT>
__global__ void gemm_scale_kernel(const float* __restrict__ A,
                                  const float* __restrict__ W,
                                  const float* __restrict__ dis,
                                  float* __restrict__ out, int n) {
    constexpr int BM = 64, BK = 8, TN = 4;
    constexpr int TX = DOUT / TN;   // 32 / 16 / 8
    constexpr int TY = 256 / TX;    // 8 / 16 / 32
    constexpr int TM = BM / TY;     // 8 / 4 / 2

    __shared__ float As[BK][BM + 1];
    __shared__ float Ws[BK][DOUT];

    int tid = threadIdx.x;
    int tx = tid % TX, ty = tid / TX;
    int row0 = blockIdx.x * BM;

    float acc[TM][TN] = {};

    for (int k0 = 0; k0 < DIN; k0 += BK) {
        // A tile: 64 rows x 8 k, 2 floats per thread, stored k-major
        {
            int r = tid >> 2;            // 0..63
            int kk = (tid & 3) * 2;      // 0,2,4,6
            int grow = row0 + r;
            float2 v = make_float2(0.f, 0.f);
            if (grow < n) v = *(const float2*)&A[grow * DIN + k0 + kk];
            As[kk][r] = v.x;
            As[kk + 1][r] = v.y;
        }
        // W tile: 8 x DOUT
#pragma unroll
        for (int i = tid; i < BK * DOUT; i += 256) {
            int kk = i / DOUT, c = i % DOUT;
            Ws[kk][c] = W[(k0 + kk) * DOUT + c];
        }
        __syncthreads();

#pragma unroll
        for (int k = 0; k < BK; k++) {
            float rm[TM];
#pragma unroll
            for (int i = 0; i < TM; i++) rm[i] = As[k][ty * TM + i];
            float4 w4 = *(const float4*)&Ws[k][tx * TN];
            float rn[TN] = {w4.x, w4.y, w4.z, w4.w};
#pragma unroll
            for (int i = 0; i < TM; i++)
#pragma unroll
                for (int j = 0; j < TN; j++) acc[i][j] += rm[i] * rn[j];
        }
        __syncthreads();
    }

#pragma unroll
    for (int i = 0; i < TM; i++) {
        int r = row0 + ty * TM + i;
        if (r < n) {
            float dv = dis[r];
            float4 o = make_float4(acc[i][0] * dv, acc[i][1] * dv,
                                   acc[i][2] * dv, acc[i][3] * dv);
            *(float4*)&out[r * DOUT + tx * TN] = o;
        }
    }
}

// ---------------------------------------------------------------------------
// One warp per node: acc = sum over in-edges of hs[src], then
// out = relu(dis[v] * (acc + hs[v]) + b)
template <int DOUT>
__global__ void gather_combine_kernel(const float* __restrict__ hs,
                                      const int* __restrict__ csr,
                                      const int* __restrict__ offsets,
                                      const float* __restrict__ b,
                                      const float* __restrict__ dis,
                                      float* __restrict__ out, int n) {
    constexpr int VW = DOUT / 32;  // 4 / 2 / 1 floats per lane
    int warp = (blockIdx.x * blockDim.x + threadIdx.x) >> 5;
    int lane = threadIdx.x & 31;
    if (warp >= n) return;
    int v = warp;
    int s0 = offsets[v], s1 = offsets[v + 1];

    float acc[VW];
#pragma unroll
    for (int j = 0; j < VW; j++) acc[j] = 0.0f;

    for (int e = s0; e < s1; e++) {
        int src = __ldg(&csr[e]);
        const float* p = hs + (size_t)src * DOUT + lane * VW;
        if constexpr (VW == 4) {
            float4 t = *(const float4*)p;
            acc[0] += t.x; acc[1] += t.y; acc[2] += t.z; acc[3] += t.w;
        } else if constexpr (VW == 2) {
            float2 t = *(const float2*)p;
            acc[0] += t.x; acc[1] += t.y;
        } else {
            acc[0] += *p;
        }
    }

    float dv = dis[v];
    const float* hp = hs + (size_t)v * DOUT + lane * VW;
    float* op = out + (size_t)v * DOUT + lane * VW;
#pragma unroll
    for (int j = 0; j < VW; j++) {
        float r = dv * (acc[j] + hp[j]) + b[lane * VW + j];
        op[j] = r > 0.0f ? r : 0.0f;
    }
}

// ---------------------------------------------------------------------------
__global__ void mlp_kernel(const float* __restrict__ x,
                           const float* __restrict__ lw0, const float* __restrict__ lb0,
                           const float* __restrict__ lw1, const float* __restrict__ lb1,
                           const float* __restrict__ lw2, const float* __restrict__ lb2,
                           float* __restrict__ s, int n) {
    __shared__ float w0[32 * 16], b0[16], w1[16 * 8], b1[8], w2[8], b2s[1];
    int t = threadIdx.x;
    for (int j = t; j < 32 * 16; j += blockDim.x) w0[j] = lw0[j];
    for (int j = t; j < 16; j += blockDim.x) b0[j] = lb0[j];
    for (int j = t; j < 16 * 8; j += blockDim.x) w1[j] = lw1[j];
    for (int j = t; j < 8; j += blockDim.x) b1[j] = lb1[j];
    for (int j = t; j < 8; j += blockDim.x) w2[j] = lw2[j];
    if (t == 0) b2s[0] = lb2[0];
    __syncthreads();

    int i = blockIdx.x * blockDim.x + t;
    if (i >= n) return;

    float xv[32];
#pragma unroll
    for (int k = 0; k < 32; k++) xv[k] = x[i * 32 + k];

    float y1[16];
#pragma unroll
    for (int j = 0; j < 16; j++) {
        float a = b0[j];
#pragma unroll
        for (int k = 0; k < 32; k++) a += xv[k] * w0[k * 16 + j];
        y1[j] = a > 0.0f ? a : 0.0f;
    }
    float y2[8];
#pragma unroll
    for (int j = 0; j < 8; j++) {
        float a = b1[j];
#pragma unroll
        for (int k = 0; k < 16; k++) a += y1[k] * w1[k * 8 + j];
        y2[j] = a > 0.0f ? a : 0.0f;
    }
    float z = b2s[0];
#pragma unroll
    for (int k = 0; k < 8; k++) z += y2[k] * w2[k];
    s[i] = 1.0f / (1.0f + expf(-z));
}

__global__ void edge_score_kernel(const int* __restrict__ pe,
                                  const float* __restrict__ s,
                                  float* __restrict__ out, int ep) {
    int i = blockIdx.x * blockDim.x + threadIdx.x;
    if (i < ep) out[i] = s[pe[2 * i]] * s[pe[2 * i + 1]];
}

// ---------------------------------------------------------------------------
extern "C" void kernel_launch(void* const* d_in, const int* in_sizes, int n_in,
                              void* d_out, int out_size) {
    const float* x   = (const float*)d_in[0];
    const int* ei    = (const int*)d_in[1];
    const int* pe    = (const int*)d_in[2];
    const float* cw0 = (const float*)d_in[3];
    const float* cb0 = (const float*)d_in[4];
    const float* cw1 = (const float*)d_in[5];
    const float* cb1 = (const float*)d_in[6];
    const float* cw2 = (const float*)d_in[7];
    const float* cb2 = (const float*)d_in[8];
    const float* lw0 = (const float*)d_in[9];
    const float* lb0 = (const float*)d_in[10];
    const float* lw1 = (const float*)d_in[11];
    const float* lb1 = (const float*)d_in[12];
    const float* lw2 = (const float*)d_in[13];
    const float* lb2 = (const float*)d_in[14];
    float* out = (float*)d_out;

    const int N  = in_sizes[0] / 128;
    const int E  = in_sizes[1] / 2;
    const int EP = out_size;

    const int* src = ei;
    const int* dst = ei + E;

    float *hs, *xb, *dis, *sc;
    int *counts, *offsets, *cursor, *csr;
    cudaGetSymbolAddress((void**)&hs, g_hs);
    cudaGetSymbolAddress((void**)&xb, g_x);
    cudaGetSymbolAddress((void**)&dis, g_dis);
    cudaGetSymbolAddress((void**)&sc, g_s);
    cudaGetSymbolAddress((void**)&counts, g_counts);
    cudaGetSymbolAddress((void**)&offsets, g_offsets);
    cudaGetSymbolAddress((void**)&cursor, g_cursor);
    cudaGetSymbolAddress((void**)&csr, g_csr);

    const int B = 256;

    // CSR build + dis (shared by all 3 conv layers)
    zero_int_kernel<<<(N + B - 1) / B, B>>>(counts, N);
    hist_kernel<<<(E + B - 1) / B, B>>>(dst, E, counts);
    scan_kernel<<<1, 1024>>>(counts, offsets, cursor, dis, N);
    fill_kernel<<<(E + B - 1) / B, B>>>(src, dst, E, cursor, csr);

    int gwarp = (N * 32 + B - 1) / B;  // 1 warp per node

    // Layer 0: 128 -> 128
    gemm_scale_kernel<128, 128><<<(N + 63) / 64, 256>>>(x, cw0, dis, hs, N);
    gather_combine_kernel<128><<<gwarp, B>>>(hs, csr, offsets, cb0, dis, xb, N);
    // Layer 1: 128 -> 64
    gemm_scale_kernel<128, 64><<<(N + 63) / 64, 256>>>(xb, cw1, dis, hs, N);
    gather_combine_kernel<64><<<gwarp, B>>>(hs, csr, offsets, cb1, dis, xb, N);
    // Layer 2: 64 -> 32
    gemm_scale_kernel<64, 32><<<(N + 63) / 64, 256>>>(xb, cw2, dis, hs, N);
    gather_combine_kernel<32><<<gwarp, B>>>(hs, csr, offsets, cb2, dis, xb, N);

    mlp_kernel<<<(N + B - 1) / B, B>>>(xb, lw0, lb0, lw1, lb1, lw2, lb2, sc, N);
    edge_score_kernel<<<(EP + B - 1) / B, B>>>(pe, sc, out, EP);
}

// round 7
// speedup vs baseline: 4.0943x; 1.3037x over previous
#include <cuda_runtime.h>
#include <math.h>

#define NMAX 50000
#define EMAX 800000
#define DMAX 128

// Scratch (device globals; no allocation in kernel_launch)
__device__ float g_hs[NMAX * DMAX];    // hs = (x@W) * dis[row]
__device__ float g_x[NMAX * DMAX];     // layer activations
__device__ float g_dis[NMAX];          // rsqrt(deg+1)
__device__ float g_s[NMAX];            // node scores
__device__ int   g_counts[NMAX];       // in-degree histogram
__device__ int   g_offsets[NMAX + 1];  // CSR row offsets
__device__ int   g_cursor[NMAX];       // fill cursors
__device__ int   g_csr[EMAX];          // CSR src indices grouped by dst
__device__ int   g_bsums[256];         // scan block partials

// ---------------------------------------------------------------------------
// f32x2 packed-FMA helpers (sm_103a dual fp32 path)
__device__ __forceinline__ unsigned long long pack2(float x) {
    unsigned long long r;
    asm("mov.b64 %0, {%1, %1};" : "=l"(r) : "f"(x));
    return r;
}
__device__ __forceinline__ void fma2(unsigned long long& d,
                                     unsigned long long a,
                                     unsigned long long b) {
    asm("fma.rn.f32x2 %0, %1, %2, %3;" : "=l"(d) : "l"(a), "l"(b), "l"(d));
}
__device__ __forceinline__ float2 unpack2(unsigned long long v) {
    float2 f;
    asm("mov.b64 {%0, %1}, %2;" : "=f"(f.x), "=f"(f.y) : "l"(v));
    return f;
}

// ---------------------------------------------------------------------------
__global__ void hist_kernel(const int* __restrict__ dst, int E, int* counts) {
    int i = blockIdx.x * blockDim.x + threadIdx.x;
    if (i < E) atomicAdd(&counts[dst[i]], 1);
}

// Two-level exclusive scan: (1) per-block sums, (2) scan partials, (3) write.
__global__ void blocksum_kernel(const int* __restrict__ counts, int* bsums, int n) {
    __shared__ int sh[256];
    int i = blockIdx.x * 256 + threadIdx.x;
    sh[threadIdx.x] = (i < n) ? counts[i] : 0;
    __syncthreads();
#pragma unroll
    for (int off = 128; off > 0; off >>= 1) {
        if (threadIdx.x < off) sh[threadIdx.x] += sh[threadIdx.x + off];
        __syncthreads();
    }
    if (threadIdx.x == 0) bsums[blockIdx.x] = sh[0];
}

__global__ void scan_bsums_kernel(int* bsums, int nb, int* offsets, int n) {
    __shared__ int sh[256];
    int t = threadIdx.x;
    int v = (t < nb) ? bsums[t] : 0;
    sh[t] = v;
    __syncthreads();
#pragma unroll
    for (int off = 1; off < 256; off <<= 1) {
        int u = (t >= off) ? sh[t - off] : 0;
        __syncthreads();
        sh[t] += u;
        __syncthreads();
    }
    if (t < nb) bsums[t] = sh[t] - v;  // exclusive
    if (t == 255) offsets[n] = sh[255];
}

__global__ void offsets_kernel(const int* __restrict__ counts,
                               const int* __restrict__ bsums,
                               int* offsets, int* cursor, float* dis, int n) {
    __shared__ int sh[256];
    int t = threadIdx.x;
    int i = blockIdx.x * 256 + t;
    int v = (i < n) ? counts[i] : 0;
    sh[t] = v;
    __syncthreads();
#pragma unroll
    for (int off = 1; off < 256; off <<= 1) {
        int u = (t >= off) ? sh[t - off] : 0;
        __syncthreads();
        sh[t] += u;
        __syncthreads();
    }
    if (i < n) {
        int o = bsums[blockIdx.x] + sh[t] - v;
        offsets[i] = o;
        cursor[i] = o;
        dis[i] = rsqrtf((float)v + 1.0f);
    }
}

__global__ void fill_kernel(const int* __restrict__ src,
                            const int* __restrict__ dst, int E,
                            int* cursor, int* csr) {
    int i = blockIdx.x * blockDim.x + threadIdx.x;
    if (i < E) {
        int pos = atomicAdd(&cursor[dst[i]], 1);
        csr[pos] = src[i];
    }
}

// ---------------------------------------------------------------------------
// Register-blocked SGEMM + row scale using packed f32x2 FMAs.
// out[r, c] = (A@W)[r, c] * dis[r].  BM=128 rows/block, 256 threads.
template <int DIN, int DOUT>
__global__ void gemm_scale_kernel(const float* __restrict__ A,
                                  const float* __restrict__ W,
                                  const float* __restrict__ dis,
                                  float* __restrict__ out, int n) {
    constexpr int BM = 128, BK = 8, TN = 8;
    constexpr int TX = DOUT / TN;   // 16 / 8 / 4
    constexpr int TY = 256 / TX;    // 16 / 32 / 64
    constexpr int TM = BM / TY;     // 8 / 4 / 2

    __shared__ float As[BK][BM + 4];
    __shared__ float Ws[BK][DOUT];

    int tid = threadIdx.x;
    int tx = tid % TX, ty = tid / TX;
    int row0 = blockIdx.x * BM;

    unsigned long long acc[TM][TN / 2] = {};  // bits 0 == {0.f, 0.f}

    for (int k0 = 0; k0 < DIN; k0 += BK) {
        // A tile: 128 rows x 8 k; one float4 per thread, stored k-major
        {
            int r = tid >> 1;
            int kk = (tid & 1) * 4;
            int grow = row0 + r;
            float4 v = make_float4(0.f, 0.f, 0.f, 0.f);
            if (grow < n) v = *(const float4*)&A[grow * DIN + k0 + kk];
            As[kk][r] = v.x;
            As[kk + 1][r] = v.y;
            As[kk + 2][r] = v.z;
            As[kk + 3][r] = v.w;
        }
        // W tile: rows k0..k0+7 are contiguous in W
        {
            const float4* wsrc = (const float4*)(W + k0 * DOUT);
            float4* wdst = (float4*)&Ws[0][0];
#pragma unroll
            for (int i = tid; i < BK * DOUT / 4; i += 256) wdst[i] = wsrc[i];
        }
        __syncthreads();

#pragma unroll
        for (int k = 0; k < BK; k++) {
            unsigned long long b2[TN / 2];
            const unsigned long long* wp =
                (const unsigned long long*)&Ws[k][tx * TN];
#pragma unroll
            for (int j = 0; j < TN / 2; j++) b2[j] = wp[j];
#pragma unroll
            for (int i = 0; i < TM; i++) {
                unsigned long long rp = pack2(As[k][ty * TM + i]);
#pragma unroll
                for (int j = 0; j < TN / 2; j++) fma2(acc[i][j], rp, b2[j]);
            }
        }
        __syncthreads();
    }

#pragma unroll
    for (int i = 0; i < TM; i++) {
        int r = row0 + ty * TM + i;
        if (r < n) {
            float dv = dis[r];
            float2 p0 = unpack2(acc[i][0]);
            float2 p1 = unpack2(acc[i][1]);
            float2 p2 = unpack2(acc[i][2]);
            float2 p3 = unpack2(acc[i][3]);
            float4 o0 = make_float4(p0.x * dv, p0.y * dv, p1.x * dv, p1.y * dv);
            float4 o1 = make_float4(p2.x * dv, p2.y * dv, p3.x * dv, p3.y * dv);
            float* op = &out[r * DOUT + tx * TN];
            *(float4*)op = o0;
            *(float4*)(op + 4) = o1;
        }
    }
}

// ---------------------------------------------------------------------------
// One warp per node, edge loop unrolled x4 with dual accumulators:
// acc = sum over in-edges of hs[src]; out = relu(dis[v]*(acc + hs[v]) + b)
template <int VW>
__device__ __forceinline__ void vload_add(const float* __restrict__ p, float* a) {
    if constexpr (VW == 4) {
        float4 t = *(const float4*)p;
        a[0] += t.x; a[1] += t.y; a[2] += t.z; a[3] += t.w;
    } else if constexpr (VW == 2) {
        float2 t = *(const float2*)p;
        a[0] += t.x; a[1] += t.y;
    } else {
        a[0] += *p;
    }
}

template <int DOUT>
__global__ void gather_combine_kernel(const float* __restrict__ hs,
                                      const int* __restrict__ csr,
                                      const int* __restrict__ offsets,
                                      const float* __restrict__ b,
                                      const float* __restrict__ dis,
                                      float* __restrict__ out, int n) {
    constexpr int VW = DOUT / 32;  // 4 / 2 / 1 floats per lane
    int warp = (blockIdx.x * blockDim.x + threadIdx.x) >> 5;
    int lane = threadIdx.x & 31;
    if (warp >= n) return;
    int v = warp;
    int s0 = offsets[v], s1 = offsets[v + 1];

    float acc0[VW] = {}, acc1[VW] = {};
    int fo = lane * VW;

    int e = s0;
    for (; e + 4 <= s1; e += 4) {
        int i0 = __ldg(&csr[e]);
        int i1 = __ldg(&csr[e + 1]);
        int i2 = __ldg(&csr[e + 2]);
        int i3 = __ldg(&csr[e + 3]);
        const float* p0 = hs + (size_t)i0 * DOUT + fo;
        const float* p1 = hs + (size_t)i1 * DOUT + fo;
        const float* p2 = hs + (size_t)i2 * DOUT + fo;
        const float* p3 = hs + (size_t)i3 * DOUT + fo;
        vload_add<VW>(p0, acc0);
        vload_add<VW>(p1, acc1);
        vload_add<VW>(p2, acc0);
        vload_add<VW>(p3, acc1);
    }
    for (; e < s1; e++) {
        int i0 = __ldg(&csr[e]);
        vload_add<VW>(hs + (size_t)i0 * DOUT + fo, acc0);
    }

    float dv = dis[v];
    const float* hp = hs + (size_t)v * DOUT + fo;
    float* op = out + (size_t)v * DOUT + fo;
#pragma unroll
    for (int j = 0; j < VW; j++) {
        float r = dv * (acc0[j] + acc1[j] + hp[j]) + b[fo + j];
        op[j] = r > 0.0f ? r : 0.0f;
    }
}

// ---------------------------------------------------------------------------
__global__ void mlp_kernel(const float* __restrict__ x,
                           const float* __restrict__ lw0, const float* __restrict__ lb0,
                           const float* __restrict__ lw1, const float* __restrict__ lb1,
                           const float* __restrict__ lw2, const float* __restrict__ lb2,
                           float* __restrict__ s, int n) {
    __shared__ float w0[32 * 16], b0[16], w1[16 * 8], b1[8], w2[8], b2s[1];
    int t = threadIdx.x;
    for (int j = t; j < 32 * 16; j += blockDim.x) w0[j] = lw0[j];
    for (int j = t; j < 16; j += blockDim.x) b0[j] = lb0[j];
    for (int j = t; j < 16 * 8; j += blockDim.x) w1[j] = lw1[j];
    for (int j = t; j < 8; j += blockDim.x) b1[j] = lb1[j];
    for (int j = t; j < 8; j += blockDim.x) w2[j] = lw2[j];
    if (t == 0) b2s[0] = lb2[0];
    __syncthreads();

    int i = blockIdx.x * blockDim.x + t;
    if (i >= n) return;

    float xv[32];
#pragma unroll
    for (int k = 0; k < 32; k++) xv[k] = x[i * 32 + k];

    float y1[16];
#pragma unroll
    for (int j = 0; j < 16; j++) {
        float a = b0[j];
#pragma unroll
        for (int k = 0; k < 32; k++) a += xv[k] * w0[k * 16 + j];
        y1[j] = a > 0.0f ? a : 0.0f;
    }
    float y2[8];
#pragma unroll
    for (int j = 0; j < 8; j++) {
        float a = b1[j];
#pragma unroll
        for (int k = 0; k < 16; k++) a += y1[k] * w1[k * 8 + j];
        y2[j] = a > 0.0f ? a : 0.0f;
    }
    float z = b2s[0];
#pragma unroll
    for (int k = 0; k < 8; k++) z += y2[k] * w2[k];
    s[i] = 1.0f / (1.0f + expf(-z));
}

__global__ void edge_score_kernel(const int* __restrict__ pe,
                                  const float* __restrict__ s,
                                  float* __restrict__ out, int ep) {
    int i = blockIdx.x * blockDim.x + threadIdx.x;
    if (i < ep) {
        int2 p = ((const int2*)pe)[i];
        out[i] = s[p.x] * s[p.y];
    }
}

// ---------------------------------------------------------------------------
extern "C" void kernel_launch(void* const* d_in, const int* in_sizes, int n_in,
                              void* d_out, int out_size) {
    const float* x   = (const float*)d_in[0];
    const int* ei    = (const int*)d_in[1];
    const int* pe    = (const int*)d_in[2];
    const float* cw0 = (const float*)d_in[3];
    const float* cb0 = (const float*)d_in[4];
    const float* cw1 = (const float*)d_in[5];
    const float* cb1 = (const float*)d_in[6];
    const float* cw2 = (const float*)d_in[7];
    const float* cb2 = (const float*)d_in[8];
    const float* lw0 = (const float*)d_in[9];
    const float* lb0 = (const float*)d_in[10];
    const float* lw1 = (const float*)d_in[11];
    const float* lb1 = (const float*)d_in[12];
    const float* lw2 = (const float*)d_in[13];
    const float* lb2 = (const float*)d_in[14];
    float* out = (float*)d_out;

    const int N  = in_sizes[0] / 128;
    const int E  = in_sizes[1] / 2;
    const int EP = out_size;

    const int* src = ei;
    const int* dst = ei + E;

    float *hs, *xb, *dis, *sc;
    int *counts, *offsets, *cursor, *csr, *bsums;
    cudaGetSymbolAddress((void**)&hs, g_hs);
    cudaGetSymbolAddress((void**)&xb, g_x);
    cudaGetSymbolAddress((void**)&dis, g_dis);
    cudaGetSymbolAddress((void**)&sc, g_s);
    cudaGetSymbolAddress((void**)&counts, g_counts);
    cudaGetSymbolAddress((void**)&offsets, g_offsets);
    cudaGetSymbolAddress((void**)&cursor, g_cursor);
    cudaGetSymbolAddress((void**)&csr, g_csr);
    cudaGetSymbolAddress((void**)&bsums, g_bsums);

    const int B = 256;
    const int NB = (N + 255) / 256;  // scan blocks (<= 256)

    // CSR build + dis (shared by all 3 conv layers)
    cudaMemsetAsync(counts, 0, N * sizeof(int));
    hist_kernel<<<(E + B - 1) / B, B>>>(dst, E, counts);
    blocksum_kernel<<<NB, 256>>>(counts, bsums, N);
    scan_bsums_kernel<<<1, 256>>>(bsums, NB, offsets, N);
    offsets_kernel<<<NB, 256>>>(counts, bsums, offsets, cursor, dis, N);
    fill_kernel<<<(E + B - 1) / B, B>>>(src, dst, E, cursor, csr);

    int gwarp = (N * 32 + B - 1) / B;  // 1 warp per node

    // Layer 0: 128 -> 128
    gemm_scale_kernel<128, 128><<<(N + 127) / 128, 256>>>(x, cw0, dis, hs, N);
    gather_combine_kernel<128><<<gwarp, B>>>(hs, csr, offsets, cb0, dis, xb, N);
    // Layer 1: 128 -> 64
    gemm_scale_kernel<128, 64><<<(N + 127) / 128, 256>>>(xb, cw1, dis, hs, N);
    gather_combine_kernel<64><<<gwarp, B>>>(hs, csr, offsets, cb1, dis, xb, N);
    // Layer 2: 64 -> 32
    gemm_scale_kernel<64, 32><<<(N + 127) / 128, 256>>>(xb, cw2, dis, hs, N);
    gather_combine_kernel<32><<<gwarp, B>>>(hs, csr, offsets, cb2, dis, xb, N);

    mlp_kernel<<<(N + B - 1) / B, B>>>(xb, lw0, lb0, lw1, lb1, lw2, lb2, sc, N);
    edge_score_kernel<<<(EP + B - 1) / B, B>>>(pe, sc, out, EP);
}